// round 17
// baseline (speedup 1.0000x reference)
#include <cuda_runtime.h>
#include <cuda_bf16.h>
#include <math_constants.h>
#include <cstdint>

// Problem shape (fixed by setup_inputs): x[4,256,64,64]
#define BB   4
#define CDIM 256
#define NDIM 4096
#define C8   32

// ---------------- scratch (static device globals; no allocation) -------------
// Q/K stored pre-split into bf16 high/low parts, pair-interleaved (kperm_bf).
__device__ __nv_bfloat16 g_Qh[BB * NDIM * C8];
__device__ __nv_bfloat16 g_Ql[BB * NDIM * C8];
__device__ __nv_bfloat16 g_Kh[BB * NDIM * C8];
__device__ __nv_bfloat16 g_Kl[BB * NDIM * C8];
__device__ float g_V2[BB * CDIM * NDIM];  // V[b][c][j], tf32-rounded, j-interleaved

// =============================================================================
// helpers
// =============================================================================
__device__ __forceinline__ uint32_t smem_u32(const void* p) {
    uint32_t a;
    asm("{ .reg .u64 t; cvta.to.shared.u64 t, %1; cvt.u32.u64 %0, t; }" : "=r"(a) : "l"(p));
    return a;
}
__device__ __forceinline__ uint32_t f2tf(float x) {
    uint32_t r;
    asm("cvt.rna.tf32.f32 %0, %1;" : "=r"(r) : "f"(x));
    return r;
}
// bf16 k16 pair interleave for Q/K gmem layout
__device__ __forceinline__ int kperm_bf(int k) {
    return (k & 16) + ((k >> 1) & 3) * 4 + ((k >> 3) & 1) * 2 + (k & 1);
}
// float-array swizzle (S/V tiles): XOR float-col by 8*(row&3)
#define SWZ(r, c) ((c) ^ (8 * ((r) & 3)))

__device__ __forceinline__ void mma_tf32(float c[4], uint32_t a0, uint32_t a1,
                                         uint32_t a2, uint32_t a3,
                                         uint32_t b0, uint32_t b1) {
    asm volatile(
        "mma.sync.aligned.m16n8k8.row.col.f32.tf32.tf32.f32 "
        "{%0,%1,%2,%3}, {%4,%5,%6,%7}, {%8,%9}, {%0,%1,%2,%3};"
        : "+f"(c[0]), "+f"(c[1]), "+f"(c[2]), "+f"(c[3])
        : "r"(a0), "r"(a1), "r"(a2), "r"(a3), "r"(b0), "r"(b1));
}
__device__ __forceinline__ void mma_bf16(float c[4], uint32_t a0, uint32_t a1,
                                         uint32_t a2, uint32_t a3,
                                         uint32_t b0, uint32_t b1) {
    asm volatile(
        "mma.sync.aligned.m16n8k16.row.col.f32.bf16.bf16.f32 "
        "{%0,%1,%2,%3}, {%4,%5,%6,%7}, {%8,%9}, {%0,%1,%2,%3};"
        : "+f"(c[0]), "+f"(c[1]), "+f"(c[2]), "+f"(c[3])
        : "r"(a0), "r"(a1), "r"(a2), "r"(a3), "r"(b0), "r"(b1));
}
__device__ __forceinline__ void cpa16(uint32_t dst, const void* src) {
    asm volatile("cp.async.cg.shared.global [%0], [%1], 16;" :: "r"(dst), "l"(src) : "memory");
}
#define CP_COMMIT() asm volatile("cp.async.commit_group;" ::: "memory")
#define CP_WAIT1()  asm volatile("cp.async.wait_group 1;" ::: "memory")
#define CP_WAIT0()  asm volatile("cp.async.wait_group 0;" ::: "memory")

// =============================================================================
// Projection. sel 0/1 (Q/K, O=32): bf16 high/low split, kperm_bf layout.
// sel 2 (V, O=256): FUSED transpose -> g_V2[b][c][kperm(j)], tf32-rounded.
// (unchanged, passing since R15)
// =============================================================================
__global__ __launch_bounds__(256) void proj_kernel(
    const float* __restrict__ x, const float* __restrict__ Wm,
    const float* __restrict__ bias, int O, int sel)
{
    __shared__ float Xs[16][128];
    __shared__ float Ws[16][64];
    __shared__ float Vt[64 * 131];   // [c_local][i_local], stride 131 (sel==2)

    const int b  = blockIdx.z;
    const int i0 = blockIdx.x * 128;
    const int o0 = blockIdx.y * 64;
    const int t  = threadIdx.x;
    const int tx = t & 15;
    const int ty = t >> 4;

    const float* xb = x + (size_t)b * CDIM * NDIM;

    float acc[8][4];
#pragma unroll
    for (int r = 0; r < 8; r++)
#pragma unroll
        for (int u = 0; u < 4; u++) acc[r][u] = 0.f;

    for (int c0 = 0; c0 < CDIM; c0 += 16) {
#pragma unroll
        for (int l = t; l < 512; l += 256) {
            int r = l >> 5, q = l & 31;
            float4 v = *reinterpret_cast<const float4*>(xb + (size_t)(c0 + r) * NDIM + i0 + q * 4);
            *reinterpret_cast<float4*>(&Xs[r][q * 4]) = v;
        }
        {
            int o = t >> 2, c4 = (t & 3) * 4;
            float4 w = make_float4(0.f, 0.f, 0.f, 0.f);
            if (o0 + o < O)
                w = *reinterpret_cast<const float4*>(Wm + (size_t)(o0 + o) * CDIM + c0 + c4);
            Ws[c4 + 0][o] = w.x; Ws[c4 + 1][o] = w.y;
            Ws[c4 + 2][o] = w.z; Ws[c4 + 3][o] = w.w;
        }
        __syncthreads();
#pragma unroll
        for (int cc = 0; cc < 16; cc++) {
            float4 a0 = *reinterpret_cast<const float4*>(&Xs[cc][ty * 8]);
            float4 a1 = *reinterpret_cast<const float4*>(&Xs[cc][ty * 8 + 4]);
            float4 bv = *reinterpret_cast<const float4*>(&Ws[cc][tx * 4]);
            float aa[8] = {a0.x, a0.y, a0.z, a0.w, a1.x, a1.y, a1.z, a1.w};
            float bb[4] = {bv.x, bv.y, bv.z, bv.w};
#pragma unroll
            for (int r = 0; r < 8; r++)
#pragma unroll
                for (int u = 0; u < 4; u++) acc[r][u] += aa[r] * bb[u];
        }
        __syncthreads();
    }

    if (sel == 2) {
        float4 bs = *reinterpret_cast<const float4*>(bias + o0 + tx * 4);
        float bb[4] = {bs.x, bs.y, bs.z, bs.w};
#pragma unroll
        for (int r = 0; r < 8; r++)
#pragma unroll
            for (int u = 0; u < 4; u++)
                Vt[(tx * 4 + u) * 131 + ty * 8 + r] = acc[r][u] + bb[u];
        __syncthreads();

        const int lane = t & 31, grp = t >> 5;
        const int Bb = lane >> 1, h = lane & 1;
        const int s0 = 8 * Bb + (h ? 2 : 0);
        const int s1 = 8 * Bb + (h ? 6 : 4);
        const int s2 = 8 * Bb + (h ? 3 : 1);
        const int s3 = 8 * Bb + (h ? 7 : 5);
#pragma unroll
        for (int rr = 0; rr < 8; rr++) {
            const int c = grp + rr * 8;
            const float* row = &Vt[c * 131];
            float4 vv;
            vv.x = __uint_as_float(f2tf(row[s0]));
            vv.y = __uint_as_float(f2tf(row[s1]));
            vv.z = __uint_as_float(f2tf(row[s2]));
            vv.w = __uint_as_float(f2tf(row[s3]));
            *reinterpret_cast<float4*>(
                g_V2 + ((size_t)(b * CDIM + o0 + c) << 12) + i0 + lane * 4) = vv;
        }
    } else if (o0 + tx * 4 < O) {
        float4 bs = *reinterpret_cast<const float4*>(bias + o0 + tx * 4);
        float bb[4] = {bs.x, bs.y, bs.z, bs.w};
        __nv_bfloat16* Oh = (sel == 0) ? g_Qh : g_Kh;
        __nv_bfloat16* Ol = (sel == 0) ? g_Ql : g_Kl;
#pragma unroll
        for (int r = 0; r < 8; r++) {
            const size_t row = ((size_t)b * NDIM + i0 + ty * 8 + r) * 32;
#pragma unroll
            for (int u = 0; u < 4; u++) {
                float v = acc[r][u] + bb[u];
                __nv_bfloat16 hb = __float2bfloat16(v);
                __nv_bfloat16 lb = __float2bfloat16(v - __bfloat162float(hb));
                int pos = kperm_bf(tx * 4 + u);
                Oh[row + pos] = hb;
                Ol[row + pos] = lb;
            }
        }
    }
}

// =============================================================================
// Flash attention, 512 THREADS (16 warps) per 128-query CTA.
// Halves per-thread register state (acc 64, sfrag 16) -> no spills under the
// 128-reg/thread ceiling; 4 warps/SMSP for latency hiding. Numerics and smem
// layout identical to R15 (per-output mma chains + den order unchanged).
// QK warp tile 16x32 (qm0=(w&7)*16, qn0=(w>>3)*32);
// PV warp tile 32x64 (pm0=(w&3)*32, pn0=(w>>2)*64).
// =============================================================================
#define QH_B    0
#define QL_B    8192
#define K_B     16384
#define KBUF_B  8192      // per buffer: KH 4096 + KL 4096
#define V_F     8192      // float index (byte 32768)
#define VBUF_F  16384     // 256 x 64 floats
#define S_F     40960     // float index (byte 163840), 128 x 64 (P tile)
#define DEN_F   49152     // float index (byte 196608), 128 x 2
#define SMEM_ATTN 197632

__global__ __launch_bounds__(512, 1) void attn_kernel(
    const float* __restrict__ x, const float* __restrict__ gamma,
    float* __restrict__ out)
{
    extern __shared__ float smf[];
    char* smc = reinterpret_cast<char*>(smf);
    const uint32_t sb = smem_u32(smf);
    const int t  = threadIdx.x;
    const int w  = t >> 5;
    const int lg = (t & 31) >> 2;
    const int l4 = t & 3;
    const int b  = blockIdx.y;
    const int i0 = blockIdx.x * 128;

    // ---- Q preload: 1024 16B-chunks (h+l), 512 threads -> 2 iters ----
#pragma unroll
    for (int it = 0; it < 2; it++) {
        int idx = it * 512 + t;
        int arr = idx >> 9;              // 0 = Qh, 1 = Ql
        int r   = (idx >> 2) & 127;
        int q   = idx & 3;
        const __nv_bfloat16* src = (arr ? g_Ql : g_Qh)
            + ((size_t)(b * NDIM + i0 + r) << 5) + q * 8;
        char* dst = smc + (arr ? QL_B : QH_B) + r * 64 + (q ^ (r & 3)) * 16;
        *reinterpret_cast<uint4*>(dst) = *reinterpret_cast<const uint4*>(src);
    }

    auto fill = [&](int tl, int buf) {
        const int j0 = tl << 6;
        const uint32_t kb = sb + K_B + buf * KBUF_B;
        const uint32_t vb = sb + V_F * 4 + buf * VBUF_F * 4;
        {   // K h+l: 512 chunks, one iteration
            int arr = t >> 8;            // 0 = Kh, 1 = Kl
            int r   = (t >> 2) & 63;
            int q   = t & 3;
            const __nv_bfloat16* src = (arr ? g_Kl : g_Kh)
                + ((size_t)(b * NDIM + j0 + r) << 5) + q * 8;
            cpa16(kb + arr * 4096 + r * 64 + (q ^ (r & 3)) * 16, src);
        }
#pragma unroll
        for (int it = 0; it < 8; it++) { // V2: 4096 chunks
            int idx = it * 512 + t;
            int cr = idx >> 4, q = idx & 15;
            cpa16(vb + (cr * 64 + SWZ(cr, q * 4)) * 4,
                  g_V2 + ((size_t)(b * CDIM + cr) << 12) + j0 + q * 4);
        }
        CP_COMMIT();
    };

    fill(0, 0);

    // PV: warp tile rows pm0..+31, cols pn0..+63
    const int pm0 = (w & 3) * 32;
    const int pn0 = (w >> 2) * 64;
    float acc[2][8][4];
#pragma unroll
    for (int mt = 0; mt < 2; mt++)
#pragma unroll
        for (int nt = 0; nt < 8; nt++)
#pragma unroll
            for (int u = 0; u < 4; u++) acc[mt][nt][u] = 0.f;

    // QK: warp tile rows qm0..+15, cols qn0..+31
    const int qm0 = (w & 7) * 16;
    const int qn0 = (w >> 3) * 32;

    float den2[2] = {0.f, 0.f};          // rows qm0+lg, qm0+lg+8 partials

    // P-store positions within 8-block for natural cols 2l4, 2l4+1
    const int pos0 = (l4 < 2) ? (4 * l4)     : (4 * l4 - 7);
    const int pos1 = (l4 < 2) ? (4 * l4 + 2) : (4 * l4 - 5);

    for (int tl = 0; tl < 64; tl++) {
        const int buf = tl & 1;
        __syncthreads();                         // B0: PV(tl-1) P/V reads done
        if (tl < 63) { fill(tl + 1, buf ^ 1); CP_WAIT1(); }
        else         { CP_WAIT0(); }
        __syncthreads();                         // B1: tile tl K/V (and Q) visible

        // ---- S = Q.K^T (bf16 split) + exp in registers + P store ----
        {
            const char* khb = smc + K_B + buf * KBUF_B;
            const char* klb = khb + 4096;
            float sfrag[4][4];
#pragma unroll
            for (int nt = 0; nt < 4; nt++)
#pragma unroll
                for (int u = 0; u < 4; u++) sfrag[nt][u] = 0.f;

            const int rA = qm0 + lg, rB = rA + 8;
#pragma unroll
            for (int kst = 0; kst < 2; kst++) {
                const int co = 32 * kst + 8 * l4;
                uint2 qh0 = *reinterpret_cast<const uint2*>(smc + QH_B + rA * 64 + (co ^ (16 * (rA & 3))));
                uint2 qh1 = *reinterpret_cast<const uint2*>(smc + QH_B + rB * 64 + (co ^ (16 * (rB & 3))));
                uint2 ql0 = *reinterpret_cast<const uint2*>(smc + QL_B + rA * 64 + (co ^ (16 * (rA & 3))));
                uint2 ql1 = *reinterpret_cast<const uint2*>(smc + QL_B + rB * 64 + (co ^ (16 * (rB & 3))));
#pragma unroll
                for (int nt = 0; nt < 4; nt++) {
                    const int jr = qn0 + nt * 8 + lg;
                    const int koff = jr * 64 + (co ^ (16 * (jr & 3)));
                    uint2 bh = *reinterpret_cast<const uint2*>(khb + koff);
                    uint2 bl = *reinterpret_cast<const uint2*>(klb + koff);
                    mma_bf16(sfrag[nt], qh0.x, qh1.x, qh0.y, qh1.y, bh.x, bh.y);
                    mma_bf16(sfrag[nt], qh0.x, qh1.x, qh0.y, qh1.y, bl.x, bl.y);
                    mma_bf16(sfrag[nt], ql0.x, ql1.x, ql0.y, ql1.y, bh.x, bh.y);
                }
            }
            // exp + tf32 round + scatter to P (k-interleaved), den partials
            float d0 = 0.f, d1 = 0.f;
#pragma unroll
            for (int nt = 0; nt < 4; nt++) {
                const int blk = qn0 + nt * 8;
                float p0 = __uint_as_float(f2tf(__expf(sfrag[nt][0])));
                float p1 = __uint_as_float(f2tf(__expf(sfrag[nt][1])));
                float p2 = __uint_as_float(f2tf(__expf(sfrag[nt][2])));
                float p3 = __uint_as_float(f2tf(__expf(sfrag[nt][3])));
                d0 += p0 + p1;
                d1 += p2 + p3;
                smf[S_F + rA * 64 + SWZ(rA, blk + pos0)] = p0;
                smf[S_F + rA * 64 + SWZ(rA, blk + pos1)] = p1;
                smf[S_F + rB * 64 + SWZ(rB, blk + pos0)] = p2;
                smf[S_F + rB * 64 + SWZ(rB, blk + pos1)] = p3;
            }
            d0 += __shfl_xor_sync(0xffffffffu, d0, 1);
            d0 += __shfl_xor_sync(0xffffffffu, d0, 2);
            d1 += __shfl_xor_sync(0xffffffffu, d1, 1);
            d1 += __shfl_xor_sync(0xffffffffu, d1, 2);
            den2[0] += d0;
            den2[1] += d1;
        }
        __syncthreads();                         // B3: P complete

        // ---- OUT += P.V  (tf32; M=128, N=256, K=64; warp 32x64) ----
        {
            const int vbb = V_F + buf * VBUF_F;
#pragma unroll
            for (int kst = 0; kst < 8; kst++) {
                const int k0 = kst * 8 + 2 * l4;
                const int ksw = SWZ(lg, k0);
                uint2 pa[2][2];
#pragma unroll
                for (int mt = 0; mt < 2; mt++) {
                    const int r0 = pm0 + mt * 16;
                    pa[mt][0] = *reinterpret_cast<const uint2*>(&smf[S_F + (r0 + lg)     * 64 + ksw]);
                    pa[mt][1] = *reinterpret_cast<const uint2*>(&smf[S_F + (r0 + lg + 8) * 64 + ksw]);
                }
#pragma unroll
                for (int nt = 0; nt < 8; nt++) {
                    const int cr = pn0 + nt * 8 + lg;
                    uint2 bv = *reinterpret_cast<const uint2*>(&smf[vbb + cr * 64 + ksw]);
#pragma unroll
                    for (int mt = 0; mt < 2; mt++)
                        mma_tf32(acc[mt][nt], pa[mt][0].x, pa[mt][1].x,
                                 pa[mt][0].y, pa[mt][1].y, bv.x, bv.y);
                }
            }
        }
    }

    // ---- den: per-(row, col-half) partials; half = w>>3 ----
    if (l4 == 0) {
        smf[DEN_F + (qm0 + lg)     * 2 + (w >> 3)] = den2[0];
        smf[DEN_F + (qm0 + lg + 8) * 2 + (w >> 3)] = den2[1];
    }
    __syncthreads();

    const float ga = gamma[0];
    const float* xb = x   + (size_t)b * CDIM * NDIM;
    float*       ob = out + (size_t)b * CDIM * NDIM;

#pragma unroll
    for (int mt = 0; mt < 2; mt++) {
        const int r0 = pm0 + mt * 16;
        const int rA = r0 + lg, rB = r0 + lg + 8;
        const float inv0 = 1.f / (smf[DEN_F + rA * 2] + smf[DEN_F + rA * 2 + 1]);
        const float inv1 = 1.f / (smf[DEN_F + rB * 2] + smf[DEN_F + rB * 2 + 1]);
        const int gi0 = i0 + rA;
#pragma unroll
        for (int nt = 0; nt < 8; nt++) {
            const int col = pn0 + nt * 8 + 2 * l4;
            const size_t b00 = (size_t)col * NDIM + gi0;
            const size_t b10 = b00 + NDIM;
            ob[b00]     = ga * (acc[mt][nt][0] * inv0) + xb[b00];
            ob[b10]     = ga * (acc[mt][nt][1] * inv0) + xb[b10];
            ob[b00 + 8] = ga * (acc[mt][nt][2] * inv1) + xb[b00 + 8];
            ob[b10 + 8] = ga * (acc[mt][nt][3] * inv1) + xb[b10 + 8];
        }
    }
}

// =============================================================================
extern "C" void kernel_launch(void* const* d_in, const int* in_sizes, int n_in,
                              void* d_out, int out_size)
{
    (void)in_sizes; (void)n_in; (void)out_size;
    const float* x     = (const float*)d_in[0];
    const float* Wq    = (const float*)d_in[1];
    const float* bq    = (const float*)d_in[2];
    const float* Wk    = (const float*)d_in[3];
    const float* bk    = (const float*)d_in[4];
    const float* Wv    = (const float*)d_in[5];
    const float* bv    = (const float*)d_in[6];
    const float* gamma = (const float*)d_in[7];
    float* out = (float*)d_out;

    (void)cudaFuncSetAttribute(attn_kernel,
                               cudaFuncAttributeMaxDynamicSharedMemorySize, SMEM_ATTN);

    dim3 gq(NDIM / 128, 1, BB);
    dim3 gv(NDIM / 128, 4, BB);
    proj_kernel<<<gq, 256>>>(x, Wq, bq, C8,   0);
    proj_kernel<<<gq, 256>>>(x, Wk, bk, C8,   1);
    proj_kernel<<<gv, 256>>>(x, Wv, bv, CDIM, 2);   // fused transpose -> g_V2

    dim3 ga(NDIM / 128, BB);    // 128 CTAs x 512 threads, 1 wave
    attn_kernel<<<ga, 512, SMEM_ATTN>>>(x, gamma, out);
}